// round 15
// baseline (speedup 1.0000x reference)
#include <cuda_runtime.h>
#include <cuda_bf16.h>
#include <cstdint>

#define BB 2
#define SS 2048
#define HH 1024
#define NH 16
#define HD 64
#define QKV_ELEMS (BB*NH*SS*HD)   // 4,194,304
#define XROWS (BB*SS)             // 4096
#define KP (HH/2)                 // 512 bf16 pairs per row (proj k-dim)
#define ZROWS (BB*NH*SS)          // 65536

// Scratch.
__device__ float    g_q[QKV_ELEMS];
__device__ float    g_k[QKV_ELEMS];
__device__ float    g_v[QKV_ELEMS];
__device__ uint32_t g_vp[QKV_ELEMS / 2];          // fp16 pairs of v along s
__device__ uint32_t g_xs[2][3][XROWS * KP];       // split query,key inputs
__device__ uint32_t g_ws[2][3][HH * KP];          // split Wq, Wk
__device__ uint32_t g_wp[(size_t)ZROWS * (SS/2)]; // fp16 pairs of w along j

// ---------------------------------------------------------------------------
// Precision helpers
// ---------------------------------------------------------------------------
// Lossless 3-way bf16 split of an fp32 pair: x = b1 + b2 + b3 exactly.
__device__ __forceinline__ void bsplit2(float x0, float x1,
                                        uint32_t& p1, uint32_t& p2, uint32_t& p3)
{
    __nv_bfloat162 t1 = __floats2bfloat162_rn(x0, x1);
    uint32_t u1; memcpy(&u1, &t1, 4);
    float a0 = __uint_as_float(u1 << 16);
    float a1 = __uint_as_float(u1 & 0xffff0000u);
    float r0 = x0 - a0, r1 = x1 - a1;
    __nv_bfloat162 t2 = __floats2bfloat162_rn(r0, r1);
    uint32_t u2; memcpy(&u2, &t2, 4);
    float b0 = __uint_as_float(u2 << 16);
    float b1 = __uint_as_float(u2 & 0xffff0000u);
    __nv_bfloat162 t3 = __floats2bfloat162_rn(r0 - b0, r1 - b1);
    uint32_t u3; memcpy(&u3, &t3, 4);
    p1 = u1; p2 = u2; p3 = u3;
}

__device__ __forceinline__ void split_tf32(float x, uint32_t& hi, uint32_t& lo) {
    uint32_t h;
    asm("cvt.rna.tf32.f32 %0, %1;" : "=r"(h) : "f"(x));
    float resid = x - __uint_as_float(h);
    uint32_t l;
    asm("cvt.rna.tf32.f32 %0, %1;" : "=r"(l) : "f"(resid));
    hi = h; lo = l;
}
__device__ __forceinline__ uint32_t f16x2(float lo, float hi) {
    uint32_t r;
    asm("cvt.rn.f16x2.f32 %0, %1, %2;" : "=r"(r) : "f"(hi), "f"(lo));
    return r;
}

#define MMA_BF16(c, a, b)                                                      \
    asm volatile("mma.sync.aligned.m16n8k16.row.col.f32.bf16.bf16.f32 "        \
        "{%0,%1,%2,%3}, {%4,%5,%6,%7}, {%8,%9}, {%0,%1,%2,%3};"                \
        : "+f"((c)[0]), "+f"((c)[1]), "+f"((c)[2]), "+f"((c)[3])               \
        : "r"((a)[0]), "r"((a)[1]), "r"((a)[2]), "r"((a)[3]),                  \
          "r"((b)[0]), "r"((b)[1]))

#define MMA_TF32(c, a, b)                                                      \
    asm volatile("mma.sync.aligned.m16n8k8.row.col.f32.tf32.tf32.f32 "         \
        "{%0,%1,%2,%3}, {%4,%5,%6,%7}, {%8,%9}, {%0,%1,%2,%3};"                \
        : "+f"((c)[0]), "+f"((c)[1]), "+f"((c)[2]), "+f"((c)[3])               \
        : "r"((a)[0]), "r"((a)[1]), "r"((a)[2]), "r"((a)[3]),                  \
          "r"((b)[0]), "r"((b)[1]))

#define MMA_F16(c, a, b)                                                       \
    asm volatile("mma.sync.aligned.m16n8k16.row.col.f32.f16.f16.f32 "          \
        "{%0,%1,%2,%3}, {%4,%5,%6,%7}, {%8,%9}, {%0,%1,%2,%3};"                \
        : "+f"((c)[0]), "+f"((c)[1]), "+f"((c)[2]), "+f"((c)[3])               \
        : "r"((a)[0]), "r"((a)[1]), "r"((a)[2]), "r"((a)[3]),                  \
          "r"((b)[0]), "r"((b)[1]))

// 6-term exact-bf16 product chain, SMALLEST TERMS FIRST (validated R9).
#define MMA6_REV(acc, a, b) do {                                               \
    MMA_BF16(acc, (a)[2], (b)[0]);                                             \
    MMA_BF16(acc, (a)[0], (b)[2]);                                             \
    MMA_BF16(acc, (a)[1], (b)[1]);                                             \
    MMA_BF16(acc, (a)[1], (b)[0]);                                             \
    MMA_BF16(acc, (a)[0], (b)[1]);                                             \
    MMA_BF16(acc, (a)[0], (b)[0]);                                             \
} while (0)

// ---------------------------------------------------------------------------
// Kernel 0: split an fp32 matrix into 3 packed-bf16 arrays (pairs along k).
// ---------------------------------------------------------------------------
__global__ __launch_bounds__(256) void split3_kernel(
    const float* __restrict__ src, uint32_t* __restrict__ d1,
    uint32_t* __restrict__ d2, uint32_t* __restrict__ d3, int npairs)
{
    int i = blockIdx.x * 256 + threadIdx.x;
    if (i >= npairs) return;
    float2 x = ((const float2*)src)[i];
    uint32_t p1, p2, p3;
    bsplit2(x.x, x.y, p1, p2, p3);
    d1[i] = p1; d2[i] = p2; d3[i] = p3;
}

// ---------------------------------------------------------------------------
// Kernel 1: q/k projection via 6xBF16 with PER-CHUNK accumulators (exact R9
// form).  128(m) x 64(n), BK=32, 8 warps 4x2.
// ---------------------------------------------------------------------------
#define PJ6_STR 20
__global__ __launch_bounds__(256) void proj6_kernel(
    const float* __restrict__ bq, const float* __restrict__ bk)
{
    __shared__ uint32_t Asp[3][128 * PJ6_STR];
    __shared__ uint32_t Bsp[3][64 * PJ6_STR];

    const int zi = blockIdx.z;                 // 0=q, 1=k
    const float* bias = zi ? bk : bq;
    const uint32_t* Xb = &g_xs[zi][0][0];
    const uint32_t* Wb = &g_ws[zi][0][0];
    float* Y = zi ? g_k : g_q;

    const int c0 = blockIdx.x * 64;            // head h = blockIdx.x
    const int r0 = blockIdx.y * 128;
    const int t    = threadIdx.x;
    const int wid  = t >> 5;
    const int lane = t & 31;
    const int gq   = lane >> 2;
    const int tq   = lane & 3;
    const int wi   = wid >> 1;
    const int wd   = wid & 1;

    float acc[2][4][4];
#pragma unroll
    for (int mt = 0; mt < 2; mt++)
#pragma unroll
        for (int nt = 0; nt < 4; nt++)
#pragma unroll
            for (int r = 0; r < 4; r++) acc[mt][nt][r] = 0.0f;

    for (int c = 0; c < KP / 16; c++) {        // 32 iters of 16 pairs (32 k)
#pragma unroll
        for (int l = 0; l < 3; l++) {
            const uint32_t* Xl = Xb + (size_t)l * XROWS * KP;
            const uint32_t* Wl = Wb + (size_t)l * HH * KP;
#pragma unroll
            for (int u = 0; u < 2; u++) {
                int g = u * 256 + t;           // 512 uint4 over 128x16
                int r = g >> 2, pq = g & 3;
                uint4 v = *(const uint4*)(Xl + (size_t)(r0 + r) * KP + c * 16 + pq * 4);
                *(uint4*)&Asp[l][r * PJ6_STR + pq * 4] = v;
            }
            {
                int r = t >> 2, pq = t & 3;    // 256 uint4 over 64x16
                uint4 v = *(const uint4*)(Wl + (size_t)(c0 + r) * KP + c * 16 + pq * 4);
                *(uint4*)&Bsp[l][r * PJ6_STR + pq * 4] = v;
            }
        }
        __syncthreads();

#pragma unroll
        for (int ks = 0; ks < 2; ks++) {       // two K=16 chunks
            const int kp = ks * 8;
            uint32_t a[3][2][4], b[3][4][2];
#pragma unroll
            for (int l = 0; l < 3; l++) {
#pragma unroll
                for (int mt = 0; mt < 2; mt++) {
                    int m = wi * 32 + mt * 16 + gq;
                    a[l][mt][0] = Asp[l][m * PJ6_STR + kp + tq];
                    a[l][mt][1] = Asp[l][(m + 8) * PJ6_STR + kp + tq];
                    a[l][mt][2] = Asp[l][m * PJ6_STR + kp + tq + 4];
                    a[l][mt][3] = Asp[l][(m + 8) * PJ6_STR + kp + tq + 4];
                }
#pragma unroll
                for (int nt = 0; nt < 4; nt++) {
                    int n = wd * 32 + nt * 8 + gq;
                    b[l][nt][0] = Bsp[l][n * PJ6_STR + kp + tq];
                    b[l][nt][1] = Bsp[l][n * PJ6_STR + kp + tq + 4];
                }
            }
#pragma unroll
            for (int mt = 0; mt < 2; mt++)
#pragma unroll
                for (int nt = 0; nt < 4; nt++) {
                    uint32_t am[3][4] = {{a[0][mt][0],a[0][mt][1],a[0][mt][2],a[0][mt][3]},
                                         {a[1][mt][0],a[1][mt][1],a[1][mt][2],a[1][mt][3]},
                                         {a[2][mt][0],a[2][mt][1],a[2][mt][2],a[2][mt][3]}};
                    uint32_t bn[3][2] = {{b[0][nt][0],b[0][nt][1]},
                                         {b[1][nt][0],b[1][nt][1]},
                                         {b[2][nt][0],b[2][nt][1]}};
                    float cacc[4] = {0.0f, 0.0f, 0.0f, 0.0f};
                    MMA6_REV(cacc, am, bn);
#pragma unroll
                    for (int r = 0; r < 4; r++) acc[mt][nt][r] += cacc[r];
                }
        }
        __syncthreads();
    }

    // Epilogue: bias + write fp32 q/k in [b,h,s,d] layout.
    const int h = blockIdx.x;
#pragma unroll
    for (int mt = 0; mt < 2; mt++) {
        int row = r0 + wi * 32 + mt * 16 + gq;
        int bidx = row / SS, s = row % SS;
#pragma unroll
        for (int nt = 0; nt < 4; nt++) {
            int dl = wd * 32 + nt * 8 + 2 * tq;
            float bs0 = bias[c0 + dl], bs1 = bias[c0 + dl + 1];
            float* d0 = Y + (((size_t)(bidx * NH + h) * SS + s) * HD + dl);
            float* d1 = Y + (((size_t)(bidx * NH + h) * SS + s + 8) * HD + dl);
            *(float2*)d0 = make_float2(acc[mt][nt][0] + bs0, acc[mt][nt][1] + bs1);
            *(float2*)d1 = make_float2(acc[mt][nt][2] + bs0, acc[mt][nt][3] + bs1);
        }
    }
}

// ---------------------------------------------------------------------------
// Kernel 1b: v projection via mma.sync 3xTF32 (error-safe, validated R7).
// ---------------------------------------------------------------------------
#define PJ_STR 36
__global__ __launch_bounds__(256) void projv_mma_kernel(
    const float* __restrict__ X, const float* __restrict__ W,
    const float* __restrict__ bias, float* __restrict__ Y)
{
    __shared__ float As[128 * PJ_STR];
    __shared__ float Bs[64 * PJ_STR];

    const int c0 = blockIdx.x * 64;
    const int r0 = blockIdx.y * 128;
    const int t    = threadIdx.x;
    const int wid  = t >> 5;
    const int lane = t & 31;
    const int gq   = lane >> 2;
    const int tq   = lane & 3;
    const int wi   = wid >> 1;
    const int wd   = wid & 1;

    float acc[2][4][4];
#pragma unroll
    for (int mt = 0; mt < 2; mt++)
#pragma unroll
        for (int nt = 0; nt < 4; nt++)
#pragma unroll
            for (int r = 0; r < 4; r++) acc[mt][nt][r] = 0.0f;

    for (int k0 = 0; k0 < HH; k0 += 32) {
#pragma unroll
        for (int u = 0; u < 4; u++) {
            int l = u * 256 + t;
            int r = l >> 3, cq = l & 7;
            float4 v = *(const float4*)(X + (size_t)(r0 + r) * HH + k0 + cq * 4);
            *(float4*)&As[r * PJ_STR + cq * 4] = v;
        }
#pragma unroll
        for (int u = 0; u < 2; u++) {
            int l = u * 256 + t;
            int r = l >> 3, cq = l & 7;
            float4 v = *(const float4*)(W + (size_t)(c0 + r) * HH + k0 + cq * 4);
            *(float4*)&Bs[r * PJ_STR + cq * 4] = v;
        }
        __syncthreads();

#pragma unroll
        for (int ks = 0; ks < 4; ks++) {
            const int kk = ks * 8;

            uint32_t ah[2][4], al[2][4];
#pragma unroll
            for (int mt = 0; mt < 2; mt++) {
                int m = wi * 32 + mt * 16 + gq;
                split_tf32(As[m * PJ_STR + kk + tq],           ah[mt][0], al[mt][0]);
                split_tf32(As[(m + 8) * PJ_STR + kk + tq],     ah[mt][1], al[mt][1]);
                split_tf32(As[m * PJ_STR + kk + tq + 4],       ah[mt][2], al[mt][2]);
                split_tf32(As[(m + 8) * PJ_STR + kk + tq + 4], ah[mt][3], al[mt][3]);
            }
            uint32_t bh[4][2], bl[4][2];
#pragma unroll
            for (int nt = 0; nt < 4; nt++) {
                int n = wd * 32 + nt * 8 + gq;
                split_tf32(Bs[n * PJ_STR + kk + tq],     bh[nt][0], bl[nt][0]);
                split_tf32(Bs[n * PJ_STR + kk + tq + 4], bh[nt][1], bl[nt][1]);
            }
#pragma unroll
            for (int mt = 0; mt < 2; mt++)
#pragma unroll
                for (int nt = 0; nt < 4; nt++) {
                    MMA_TF32(acc[mt][nt], ah[mt], bh[nt]);
                    MMA_TF32(acc[mt][nt], ah[mt], bl[nt]);
                    MMA_TF32(acc[mt][nt], al[mt], bh[nt]);
                }
        }
        __syncthreads();
    }

    const int h = c0 / HD;
#pragma unroll
    for (int mt = 0; mt < 2; mt++) {
        int row = r0 + wi * 32 + mt * 16 + gq;
        int b = row / SS, s = row % SS;
#pragma unroll
        for (int nt = 0; nt < 4; nt++) {
            int dl = wd * 32 + nt * 8 + 2 * tq;
            float bs0 = bias[c0 + dl];
            float bs1 = bias[c0 + dl + 1];
            float* d0 = Y + (((size_t)(b * NH + h) * SS + s) * HD + dl);
            float* d1 = Y + (((size_t)(b * NH + h) * SS + s + 8) * HD + dl);
            *(float2*)d0 = make_float2(acc[mt][nt][0] + bs0, acc[mt][nt][1] + bs1);
            *(float2*)d1 = make_float2(acc[mt][nt][2] + bs0, acc[mt][nt][3] + bs1);
        }
    }
}

// ---------------------------------------------------------------------------
// Kernel 1c: pack v into fp16 pairs along s.
// ---------------------------------------------------------------------------
__global__ __launch_bounds__(256) void pack_v_kernel()
{
    int u = blockIdx.x * 256 + threadIdx.x;
    int s2row = u >> 4;
    int cq = u & 15;
    const float* p = g_v + (size_t)s2row * 128 + cq * 4;
    float4 a = *(const float4*)p;
    float4 b = *(const float4*)(p + 64);
    uint4 o = make_uint4(f16x2(a.x, b.x), f16x2(a.y, b.y),
                         f16x2(a.z, b.z), f16x2(a.w, b.w));
    *(uint4*)(g_vp + (size_t)s2row * 64 + cq * 4) = o;
}

// ---------------------------------------------------------------------------
// Kernel 2: scores = q @ k^T / 8 + mask via mma.sync 3xTF32 (exact R9 form).
// ---------------------------------------------------------------------------
#define SQ_STR 68
#define SC_SMEM_BYTES (192 * SQ_STR * 4 + 64 * 4)

__global__ __launch_bounds__(256) void scores_mma_kernel(
    const int* __restrict__ mask, float* __restrict__ wbuf)
{
    extern __shared__ float smem[];
    float* Qs = smem;
    float* Ks = smem + 128 * SQ_STR;
    int*   msk = (int*)(smem + 192 * SQ_STR);

    const int j0 = blockIdx.x * 64;
    const int i0 = blockIdx.y * 128;
    const int z  = blockIdx.z;
    const int bidx = z / NH;
    const int t    = threadIdx.x;
    const int wid  = t >> 5;
    const int lane = t & 31;
    const int gq   = lane >> 2;
    const int tq   = lane & 3;
    const int wi   = wid >> 1;
    const int wd   = wid & 1;

    const float* qbase = g_q + ((size_t)z * SS + i0) * HD;
    const float* kbase = g_k + ((size_t)z * SS + j0) * HD;

#pragma unroll
    for (int u = 0; u < 8; u++) {
        int l = u * 256 + t;
        int r = l >> 4, cq = l & 15;
        float4 v = ((const float4*)qbase)[l];
        *(float4*)&Qs[r * SQ_STR + cq * 4] = v;
    }
#pragma unroll
    for (int u = 0; u < 4; u++) {
        int l = u * 256 + t;
        int r = l >> 4, cq = l & 15;
        float4 v = ((const float4*)kbase)[l];
        *(float4*)&Ks[r * SQ_STR + cq * 4] = v;
    }
    if (t < 64) msk[t] = mask[(size_t)bidx * SS + j0 + t];
    __syncthreads();

    float acc[2][4][4];
#pragma unroll
    for (int mt = 0; mt < 2; mt++)
#pragma unroll
        for (int nt = 0; nt < 4; nt++)
#pragma unroll
            for (int r = 0; r < 4; r++) acc[mt][nt][r] = 0.0f;

#pragma unroll
    for (int ks = 0; ks < 8; ks++) {
        const int kk = ks * 8;

        uint32_t ah[2][4], al[2][4];
#pragma unroll
        for (int mt = 0; mt < 2; mt++) {
            int m = wi * 32 + mt * 16 + gq;
            split_tf32(Qs[m * SQ_STR + kk + tq],           ah[mt][0], al[mt][0]);
            split_tf32(Qs[(m + 8) * SQ_STR + kk + tq],     ah[mt][1], al[mt][1]);
            split_tf32(Qs[m * SQ_STR + kk + tq + 4],       ah[mt][2], al[mt][2]);
            split_tf32(Qs[(m + 8) * SQ_STR + kk + tq + 4], ah[mt][3], al[mt][3]);
        }
        uint32_t bh[4][2], bl[4][2];
#pragma unroll
        for (int nt = 0; nt < 4; nt++) {
            int n = wd * 32 + nt * 8 + gq;
            split_tf32(Ks[n * SQ_STR + kk + tq],     bh[nt][0], bl[nt][0]);
            split_tf32(Ks[n * SQ_STR + kk + tq + 4], bh[nt][1], bl[nt][1]);
        }
#pragma unroll
        for (int mt = 0; mt < 2; mt++)
#pragma unroll
            for (int nt = 0; nt < 4; nt++) {
                MMA_TF32(acc[mt][nt], ah[mt], bh[nt]);
                MMA_TF32(acc[mt][nt], ah[mt], bl[nt]);
                MMA_TF32(acc[mt][nt], al[mt], bh[nt]);
            }
    }

    const float NEG_INF = __int_as_float(0xff800000);
#pragma unroll
    for (int mt = 0; mt < 2; mt++) {
        int r = i0 + wi * 32 + mt * 16 + gq;
#pragma unroll
        for (int nt = 0; nt < 4; nt++) {
            int jl = wd * 32 + nt * 8 + 2 * tq;
            int m0 = msk[jl], m1 = msk[jl + 1];
            float v0 = (m0 > 0) ? NEG_INF : acc[mt][nt][0] * 0.125f;
            float v1 = (m1 > 0) ? NEG_INF : acc[mt][nt][1] * 0.125f;
            float v2 = (m0 > 0) ? NEG_INF : acc[mt][nt][2] * 0.125f;
            float v3 = (m1 > 0) ? NEG_INF : acc[mt][nt][3] * 0.125f;
            float* d0 = wbuf + ((size_t)z * SS + r) * SS + j0 + jl;
            float* d1 = wbuf + ((size_t)z * SS + r + 8) * SS + j0 + jl;
            *(float2*)d0 = make_float2(v0, v1);
            *(float2*)d1 = make_float2(v2, v3);
        }
    }
}

// ---------------------------------------------------------------------------
// Kernel 3: softmax + threshold + L1 renorm (divide-free); ALSO emits
// fp16-packed w pairs (R12/R14-validated; av output bit-identical).
// ---------------------------------------------------------------------------
__device__ __forceinline__ float warpMax(float v) {
#pragma unroll
    for (int o = 16; o; o >>= 1) v = fmaxf(v, __shfl_xor_sync(0xffffffffu, v, o));
    return v;
}
__device__ __forceinline__ float warpSum(float v) {
#pragma unroll
    for (int o = 16; o; o >>= 1) v += __shfl_xor_sync(0xffffffffu, v, o);
    return v;
}
__device__ float blockMax(float v, float* red) {
    v = warpMax(v);
    int w = threadIdx.x >> 5, lane = threadIdx.x & 31;
    if (lane == 0) red[w] = v;
    __syncthreads();
    float r = (lane < 8) ? red[lane] : __int_as_float(0xff800000);
    if (w == 0) { r = warpMax(r); if (lane == 0) red[0] = r; }
    __syncthreads();
    float out = red[0];
    __syncthreads();
    return out;
}
__device__ float blockSum(float v, float* red) {
    v = warpSum(v);
    int w = threadIdx.x >> 5, lane = threadIdx.x & 31;
    if (lane == 0) red[w] = v;
    __syncthreads();
    float r = (lane < 8) ? red[lane] : 0.0f;
    if (w == 0) { r = warpSum(r); if (lane == 0) red[0] = r; }
    __syncthreads();
    float out = red[0];
    __syncthreads();
    return out;
}

__global__ __launch_bounds__(256) void softmax_kernel(float* __restrict__ wbuf)
{
    __shared__ float red[8];
    const size_t row = blockIdx.x;
    float* p = wbuf + row * SS;
    uint32_t* wp = g_wp + row * (SS / 2);
    const int t = threadIdx.x;

    float4 x0 = ((const float4*)p)[t];
    float4 x1 = ((const float4*)p)[t + 256];
    float v[8] = {x0.x, x0.y, x0.z, x0.w, x1.x, x1.y, x1.z, x1.w};

    float m = v[0];
#pragma unroll
    for (int i = 1; i < 8; i++) m = fmaxf(m, v[i]);
    m = blockMax(m, red);

    float e[8], es = 0.0f;
#pragma unroll
    for (int i = 0; i < 8; i++) { e[i] = expf(v[i] - m); es += e[i]; }
    es = blockSum(es, red);

    const float tes = 0.001f * es;
    const float inv_es = 1.0f / es;

    float w[8], l1 = 0.0f;
#pragma unroll
    for (int i = 0; i < 8; i++) {
        float wi = (e[i] < tes) ? 0.0f : e[i] * inv_es;
        w[i] = wi;
        l1 += wi;
    }
    l1 = blockSum(l1, red);
    float rinv = 1.0f / fmaxf(l1, 1e-12f);

#pragma unroll
    for (int i = 0; i < 8; i++) w[i] *= rinv;

    float4 o0 = make_float4(w[0], w[1], w[2], w[3]);
    float4 o1 = make_float4(w[4], w[5], w[6], w[7]);
    ((float4*)p)[t]       = o0;
    ((float4*)p)[t + 256] = o1;

    uint2 h0 = make_uint2(f16x2(w[0], w[1]), f16x2(w[2], w[3]));
    uint2 h1 = make_uint2(f16x2(w[4], w[5]), f16x2(w[6], w[7]));
    *(uint2*)(wp + 2 * t)       = h0;
    *(uint2*)(wp + 512 + 2 * t) = h1;
}

// ---------------------------------------------------------------------------
// Kernel 4: out = w @ v via fp16 mma.sync reading pre-packed fp16 w,
// now DOUBLE-BUFFERED: LDG for chunk c+1 issues before MMAs on chunk c,
// STS lands in the alternate buffer, one __syncthreads per iteration.
// Math/order identical -> out bit-identical to R14.
// ---------------------------------------------------------------------------
#define AVW_STR 20
#define AVV_STR 72

__global__ __launch_bounds__(256) void av_f16_kernel(float* __restrict__ out)
{
    __shared__ uint32_t Wh[2][128 * AVW_STR];   // 2 x 10240 B
    __shared__ uint32_t Vp[2][16 * AVV_STR];    // 2 x 4608 B

    const int t    = threadIdx.x;
    const int wid  = t >> 5;
    const int lane = t & 31;
    const int gq   = lane >> 2;
    const int tq   = lane & 3;
    const int wi   = wid >> 1;
    const int wd   = wid & 1;

    const int i0 = blockIdx.x * 128;
    const int z  = blockIdx.y;
    const int bidx = z / NH;
    const int h    = z % NH;

    const uint32_t* Wp16   = g_wp + ((size_t)z * SS + i0) * (SS / 2);
    const uint32_t* Vpbase = g_vp + (size_t)z * (SS / 2) * HD;

    // Per-thread load coordinates (fixed across chunks)
    const int wr0 = t >> 2,  wq0 = (t & 3);            // w tile part 0
    const int wr1 = (256 + t) >> 2, wq1 = ((256 + t) & 3);
    const int vr  = t >> 4,  vq = t & 15;              // v tile

    float acc[2][4][4];
#pragma unroll
    for (int mt = 0; mt < 2; mt++)
#pragma unroll
        for (int nt = 0; nt < 4; nt++)
#pragma unroll
            for (int r = 0; r < 4; r++) acc[mt][nt][r] = 0.0f;

    // Prologue: load chunk 0 into buffer 0.
    {
        uint4 w0 = *(const uint4*)(Wp16 + (size_t)wr0 * (SS / 2) + wq0 * 4);
        uint4 w1 = *(const uint4*)(Wp16 + (size_t)wr1 * (SS / 2) + wq1 * 4);
        uint4 vv = *(const uint4*)(Vpbase + (size_t)vr * HD + vq * 4);
        *(uint4*)&Wh[0][wr0 * AVW_STR + wq0 * 4] = w0;
        *(uint4*)&Wh[0][wr1 * AVW_STR + wq1 * 4] = w1;
        *(uint4*)&Vp[0][vr * AVV_STR + vq * 4] = vv;
    }
    __syncthreads();

    for (int c = 0; c < SS / 32; c++) {
        const int cur = c & 1;
        const int nxt = cur ^ 1;
        const bool has = (c + 1 < SS / 32);

        // Prefetch chunk c+1 (LDG issues now; latency overlaps MMAs below).
        uint4 w0n, w1n, vvn;
        if (has) {
            int cc = c + 1;
            w0n = *(const uint4*)(Wp16 + (size_t)wr0 * (SS / 2) + cc * 16 + wq0 * 4);
            w1n = *(const uint4*)(Wp16 + (size_t)wr1 * (SS / 2) + cc * 16 + wq1 * 4);
            vvn = *(const uint4*)(Vpbase + (size_t)(cc * 16 + vr) * HD + vq * 4);
        }

#pragma unroll
        for (int ks = 0; ks < 2; ks++) {
            uint32_t a[2][4];
#pragma unroll
            for (int mt = 0; mt < 2; mt++) {
                int m = wi * 32 + mt * 16 + gq;
                a[mt][0] = Wh[cur][m * AVW_STR + ks * 8 + tq];
                a[mt][1] = Wh[cur][(m + 8) * AVW_STR + ks * 8 + tq];
                a[mt][2] = Wh[cur][m * AVW_STR + ks * 8 + tq + 4];
                a[mt][3] = Wh[cur][(m + 8) * AVW_STR + ks * 8 + tq + 4];
            }
            uint32_t b[4][2];
#pragma unroll
            for (int nt = 0; nt < 4; nt++) {
                int n = wd * 32 + nt * 8 + gq;
                b[nt][0] = Vp[cur][(ks * 8 + tq) * AVV_STR + n];
                b[nt][1] = Vp[cur][(ks * 8 + tq + 4) * AVV_STR + n];
            }
#pragma unroll
            for (int mt = 0; mt < 2; mt++)
#pragma unroll
                for (int nt = 0; nt < 4; nt++)
                    MMA_F16(acc[mt][nt], a[mt], b[nt]);
        }

        if (has) {
            *(uint4*)&Wh[nxt][wr0 * AVW_STR + wq0 * 4] = w0n;
            *(uint4*)&Wh[nxt][wr1 * AVW_STR + wq1 * 4] = w1n;
            *(uint4*)&Vp[nxt][vr * AVV_STR + vq * 4] = vvn;
        }
        __syncthreads();
    }

#pragma unroll
    for (int mt = 0; mt < 2; mt++) {
        int row = i0 + wi * 32 + mt * 16 + gq;
#pragma unroll
        for (int nt = 0; nt < 4; nt++) {
            int col = h * HD + wd * 32 + nt * 8 + 2 * tq;
            float* d0 = out + ((size_t)bidx * SS + row) * HH + col;
            float* d1 = out + ((size_t)bidx * SS + row + 8) * HH + col;
            *(float2*)d0 = make_float2(acc[mt][nt][0], acc[mt][nt][1]);
            *(float2*)d1 = make_float2(acc[mt][nt][2], acc[mt][nt][3]);
        }
    }
}

// ---------------------------------------------------------------------------
extern "C" void kernel_launch(void* const* d_in, const int* in_sizes, int n_in,
                              void* d_out, int out_size)
{
    const float* query = (const float*)d_in[0];
    const float* key   = (const float*)d_in[1];
    const float* value = (const float*)d_in[2];
    const int*   mask  = (const int*)  d_in[3];
    const float* Wq    = (const float*)d_in[4];
    const float* bq    = (const float*)d_in[5];
    const float* Wk    = (const float*)d_in[6];
    const float* bk    = (const float*)d_in[7];
    const float* Wv    = (const float*)d_in[8];
    const float* bv    = (const float*)d_in[9];

    float* out  = (float*)d_out;
    float* wbuf = out + (size_t)BB * SS * HH;

    float* vp;
    cudaGetSymbolAddress((void**)&vp, g_v);
    uint32_t* xs;
    cudaGetSymbolAddress((void**)&xs, g_xs);
    uint32_t* ws;
    cudaGetSymbolAddress((void**)&ws, g_ws);

    const size_t XN = (size_t)XROWS * KP;
    const size_t WN = (size_t)HH * KP;

    // 0) Split query/key inputs + Wq/Wk into lossless bf16 triples
    int xb = (int)((XN + 255) / 256);
    int wb = (int)((WN + 255) / 256);
    split3_kernel<<<xb, 256>>>(query, xs,        xs + XN,   xs + 2*XN, (int)XN);
    split3_kernel<<<xb, 256>>>(key,   xs + 3*XN, xs + 4*XN, xs + 5*XN, (int)XN);
    split3_kernel<<<wb, 256>>>(Wq,    ws,        ws + WN,   ws + 2*WN, (int)WN);
    split3_kernel<<<wb, 256>>>(Wk,    ws + 3*WN, ws + 4*WN, ws + 5*WN, (int)WN);

    // 1) q/k projections via 6xBF16 with per-chunk accumulators (R9)
    dim3 gProj(HH / 64, XROWS / 128, 2);        // (16, 32, 2)
    proj6_kernel<<<gProj, 256>>>(bq, bk);

    // 1b) v projection via 3xTF32 (error-safe)
    dim3 gProjV(HH / 64, XROWS / 128);          // (16, 32)
    projv_mma_kernel<<<gProjV, 256>>>(value, Wv, bv, vp);

    // 1c) pack v -> fp16 pairs
    pack_v_kernel<<<(QKV_ELEMS / 8) / 256, 256>>>();

    // 2) Scores via 3xTF32 mma.sync (R9)
    cudaFuncSetAttribute(scores_mma_kernel,
                         cudaFuncAttributeMaxDynamicSharedMemorySize,
                         SC_SMEM_BYTES);
    dim3 gScores(SS / 64, SS / 128, BB * NH);   // (32, 16, 32)
    scores_mma_kernel<<<gScores, 256, SC_SMEM_BYTES>>>(mask, wbuf);

    // 3) Softmax + threshold + L1 renorm; emits fp32 w + fp16-packed w
    softmax_kernel<<<BB * NH * SS, 256>>>(wbuf);

    // 4) out = w @ v via fp16 mma.sync (double-buffered, reads fp16 w)
    dim3 gAV(SS / 128, BB * NH);
    av_f16_kernel<<<gAV, 256>>>(out);
}

// round 16
// speedup vs baseline: 1.0061x; 1.0061x over previous
#include <cuda_runtime.h>
#include <cuda_bf16.h>
#include <cstdint>

#define BB 2
#define SS 2048
#define HH 1024
#define NH 16
#define HD 64
#define QKV_ELEMS (BB*NH*SS*HD)   // 4,194,304
#define XROWS (BB*SS)             // 4096
#define KP (HH/2)                 // 512 bf16 pairs per row (proj k-dim)
#define ZROWS (BB*NH*SS)          // 65536

// Scratch.
__device__ float    g_q[QKV_ELEMS];
__device__ float    g_k[QKV_ELEMS];
__device__ float    g_v[QKV_ELEMS];
__device__ uint32_t g_vp[QKV_ELEMS / 2];          // fp16 pairs of v along s
__device__ uint32_t g_xs[2][3][XROWS * KP];       // split query,key inputs
__device__ uint32_t g_ws[2][3][HH * KP];          // split Wq, Wk
__device__ uint32_t g_wp[(size_t)ZROWS * (SS/2)]; // fp16 pairs of w along j

// ---------------------------------------------------------------------------
// Precision helpers
// ---------------------------------------------------------------------------
// Lossless 3-way bf16 split of an fp32 pair: x = b1 + b2 + b3 exactly.
__device__ __forceinline__ void bsplit2(float x0, float x1,
                                        uint32_t& p1, uint32_t& p2, uint32_t& p3)
{
    __nv_bfloat162 t1 = __floats2bfloat162_rn(x0, x1);
    uint32_t u1; memcpy(&u1, &t1, 4);
    float a0 = __uint_as_float(u1 << 16);
    float a1 = __uint_as_float(u1 & 0xffff0000u);
    float r0 = x0 - a0, r1 = x1 - a1;
    __nv_bfloat162 t2 = __floats2bfloat162_rn(r0, r1);
    uint32_t u2; memcpy(&u2, &t2, 4);
    float b0 = __uint_as_float(u2 << 16);
    float b1 = __uint_as_float(u2 & 0xffff0000u);
    __nv_bfloat162 t3 = __floats2bfloat162_rn(r0 - b0, r1 - b1);
    uint32_t u3; memcpy(&u3, &t3, 4);
    p1 = u1; p2 = u2; p3 = u3;
}

__device__ __forceinline__ void split_tf32(float x, uint32_t& hi, uint32_t& lo) {
    uint32_t h;
    asm("cvt.rna.tf32.f32 %0, %1;" : "=r"(h) : "f"(x));
    float resid = x - __uint_as_float(h);
    uint32_t l;
    asm("cvt.rna.tf32.f32 %0, %1;" : "=r"(l) : "f"(resid));
    hi = h; lo = l;
}
__device__ __forceinline__ uint32_t f16x2(float lo, float hi) {
    uint32_t r;
    asm("cvt.rn.f16x2.f32 %0, %1, %2;" : "=r"(r) : "f"(hi), "f"(lo));
    return r;
}

#define MMA_BF16(c, a, b)                                                      \
    asm volatile("mma.sync.aligned.m16n8k16.row.col.f32.bf16.bf16.f32 "        \
        "{%0,%1,%2,%3}, {%4,%5,%6,%7}, {%8,%9}, {%0,%1,%2,%3};"                \
        : "+f"((c)[0]), "+f"((c)[1]), "+f"((c)[2]), "+f"((c)[3])               \
        : "r"((a)[0]), "r"((a)[1]), "r"((a)[2]), "r"((a)[3]),                  \
          "r"((b)[0]), "r"((b)[1]))

#define MMA_TF32(c, a, b)                                                      \
    asm volatile("mma.sync.aligned.m16n8k8.row.col.f32.tf32.tf32.f32 "         \
        "{%0,%1,%2,%3}, {%4,%5,%6,%7}, {%8,%9}, {%0,%1,%2,%3};"                \
        : "+f"((c)[0]), "+f"((c)[1]), "+f"((c)[2]), "+f"((c)[3])               \
        : "r"((a)[0]), "r"((a)[1]), "r"((a)[2]), "r"((a)[3]),                  \
          "r"((b)[0]), "r"((b)[1]))

#define MMA_F16(c, a, b)                                                       \
    asm volatile("mma.sync.aligned.m16n8k16.row.col.f32.f16.f16.f32 "          \
        "{%0,%1,%2,%3}, {%4,%5,%6,%7}, {%8,%9}, {%0,%1,%2,%3};"                \
        : "+f"((c)[0]), "+f"((c)[1]), "+f"((c)[2]), "+f"((c)[3])               \
        : "r"((a)[0]), "r"((a)[1]), "r"((a)[2]), "r"((a)[3]),                  \
          "r"((b)[0]), "r"((b)[1]))

// 6-term exact-bf16 product chain, SMALLEST TERMS FIRST (validated R9).
#define MMA6_REV(acc, a, b) do {                                               \
    MMA_BF16(acc, (a)[2], (b)[0]);                                             \
    MMA_BF16(acc, (a)[0], (b)[2]);                                             \
    MMA_BF16(acc, (a)[1], (b)[1]);                                             \
    MMA_BF16(acc, (a)[1], (b)[0]);                                             \
    MMA_BF16(acc, (a)[0], (b)[1]);                                             \
    MMA_BF16(acc, (a)[0], (b)[0]);                                             \
} while (0)

// ---------------------------------------------------------------------------
// Kernel 0: fused split of all four fp32 matrices (query,key,Wq,Wk) into
// lossless bf16 triples.  Same per-element bsplit2 -> bit-identical outputs;
// one launch instead of four.
// ---------------------------------------------------------------------------
#define XN ((size_t)XROWS * KP)   // 2,097,152 pairs
#define WN ((size_t)HH * KP)      //   524,288 pairs
#define TOTAL_PAIRS (2 * XN + 2 * WN)

__global__ __launch_bounds__(256) void split3_all_kernel(
    const float* __restrict__ query, const float* __restrict__ key,
    const float* __restrict__ Wq,    const float* __restrict__ Wk)
{
    size_t i = (size_t)blockIdx.x * 256 + threadIdx.x;
    if (i >= TOTAL_PAIRS) return;

    const float* src;
    uint32_t *d1, *d2, *d3;
    size_t off;
    if (i < XN)                    { src = query; off = i;
                                     d1 = &g_xs[0][0][0]; d2 = &g_xs[0][1][0]; d3 = &g_xs[0][2][0]; }
    else if (i < 2 * XN)           { src = key;   off = i - XN;
                                     d1 = &g_xs[1][0][0]; d2 = &g_xs[1][1][0]; d3 = &g_xs[1][2][0]; }
    else if (i < 2 * XN + WN)      { src = Wq;    off = i - 2 * XN;
                                     d1 = &g_ws[0][0][0]; d2 = &g_ws[0][1][0]; d3 = &g_ws[0][2][0]; }
    else                           { src = Wk;    off = i - 2 * XN - WN;
                                     d1 = &g_ws[1][0][0]; d2 = &g_ws[1][1][0]; d3 = &g_ws[1][2][0]; }

    float2 x = ((const float2*)src)[off];
    uint32_t p1, p2, p3;
    bsplit2(x.x, x.y, p1, p2, p3);
    d1[off] = p1; d2[off] = p2; d3[off] = p3;
}

// ---------------------------------------------------------------------------
// Kernel 1: q/k projection via 6xBF16 with PER-CHUNK accumulators (exact R9
// form).  128(m) x 64(n), BK=32, 8 warps 4x2.
// ---------------------------------------------------------------------------
#define PJ6_STR 20
__global__ __launch_bounds__(256) void proj6_kernel(
    const float* __restrict__ bq, const float* __restrict__ bk)
{
    __shared__ uint32_t Asp[3][128 * PJ6_STR];
    __shared__ uint32_t Bsp[3][64 * PJ6_STR];

    const int zi = blockIdx.z;                 // 0=q, 1=k
    const float* bias = zi ? bk : bq;
    const uint32_t* Xb = &g_xs[zi][0][0];
    const uint32_t* Wb = &g_ws[zi][0][0];
    float* Y = zi ? g_k : g_q;

    const int c0 = blockIdx.x * 64;            // head h = blockIdx.x
    const int r0 = blockIdx.y * 128;
    const int t    = threadIdx.x;
    const int wid  = t >> 5;
    const int lane = t & 31;
    const int gq   = lane >> 2;
    const int tq   = lane & 3;
    const int wi   = wid >> 1;
    const int wd   = wid & 1;

    float acc[2][4][4];
#pragma unroll
    for (int mt = 0; mt < 2; mt++)
#pragma unroll
        for (int nt = 0; nt < 4; nt++)
#pragma unroll
            for (int r = 0; r < 4; r++) acc[mt][nt][r] = 0.0f;

    for (int c = 0; c < KP / 16; c++) {        // 32 iters of 16 pairs (32 k)
#pragma unroll
        for (int l = 0; l < 3; l++) {
            const uint32_t* Xl = Xb + (size_t)l * XROWS * KP;
            const uint32_t* Wl = Wb + (size_t)l * HH * KP;
#pragma unroll
            for (int u = 0; u < 2; u++) {
                int g = u * 256 + t;           // 512 uint4 over 128x16
                int r = g >> 2, pq = g & 3;
                uint4 v = *(const uint4*)(Xl + (size_t)(r0 + r) * KP + c * 16 + pq * 4);
                *(uint4*)&Asp[l][r * PJ6_STR + pq * 4] = v;
            }
            {
                int r = t >> 2, pq = t & 3;    // 256 uint4 over 64x16
                uint4 v = *(const uint4*)(Wl + (size_t)(c0 + r) * KP + c * 16 + pq * 4);
                *(uint4*)&Bsp[l][r * PJ6_STR + pq * 4] = v;
            }
        }
        __syncthreads();

#pragma unroll
        for (int ks = 0; ks < 2; ks++) {       // two K=16 chunks
            const int kp = ks * 8;
            uint32_t a[3][2][4], b[3][4][2];
#pragma unroll
            for (int l = 0; l < 3; l++) {
#pragma unroll
                for (int mt = 0; mt < 2; mt++) {
                    int m = wi * 32 + mt * 16 + gq;
                    a[l][mt][0] = Asp[l][m * PJ6_STR + kp + tq];
                    a[l][mt][1] = Asp[l][(m + 8) * PJ6_STR + kp + tq];
                    a[l][mt][2] = Asp[l][m * PJ6_STR + kp + tq + 4];
                    a[l][mt][3] = Asp[l][(m + 8) * PJ6_STR + kp + tq + 4];
                }
#pragma unroll
                for (int nt = 0; nt < 4; nt++) {
                    int n = wd * 32 + nt * 8 + gq;
                    b[l][nt][0] = Bsp[l][n * PJ6_STR + kp + tq];
                    b[l][nt][1] = Bsp[l][n * PJ6_STR + kp + tq + 4];
                }
            }
#pragma unroll
            for (int mt = 0; mt < 2; mt++)
#pragma unroll
                for (int nt = 0; nt < 4; nt++) {
                    uint32_t am[3][4] = {{a[0][mt][0],a[0][mt][1],a[0][mt][2],a[0][mt][3]},
                                         {a[1][mt][0],a[1][mt][1],a[1][mt][2],a[1][mt][3]},
                                         {a[2][mt][0],a[2][mt][1],a[2][mt][2],a[2][mt][3]}};
                    uint32_t bn[3][2] = {{b[0][nt][0],b[0][nt][1]},
                                         {b[1][nt][0],b[1][nt][1]},
                                         {b[2][nt][0],b[2][nt][1]}};
                    float cacc[4] = {0.0f, 0.0f, 0.0f, 0.0f};
                    MMA6_REV(cacc, am, bn);
#pragma unroll
                    for (int r = 0; r < 4; r++) acc[mt][nt][r] += cacc[r];
                }
        }
        __syncthreads();
    }

    // Epilogue: bias + write fp32 q/k in [b,h,s,d] layout.
    const int h = blockIdx.x;
#pragma unroll
    for (int mt = 0; mt < 2; mt++) {
        int row = r0 + wi * 32 + mt * 16 + gq;
        int bidx = row / SS, s = row % SS;
#pragma unroll
        for (int nt = 0; nt < 4; nt++) {
            int dl = wd * 32 + nt * 8 + 2 * tq;
            float bs0 = bias[c0 + dl], bs1 = bias[c0 + dl + 1];
            float* d0 = Y + (((size_t)(bidx * NH + h) * SS + s) * HD + dl);
            float* d1 = Y + (((size_t)(bidx * NH + h) * SS + s + 8) * HD + dl);
            *(float2*)d0 = make_float2(acc[mt][nt][0] + bs0, acc[mt][nt][1] + bs1);
            *(float2*)d1 = make_float2(acc[mt][nt][2] + bs0, acc[mt][nt][3] + bs1);
        }
    }
}

// ---------------------------------------------------------------------------
// Kernel 1b: v projection via mma.sync 3xTF32 (error-safe, validated R7).
// ---------------------------------------------------------------------------
#define PJ_STR 36
__global__ __launch_bounds__(256) void projv_mma_kernel(
    const float* __restrict__ X, const float* __restrict__ W,
    const float* __restrict__ bias, float* __restrict__ Y)
{
    __shared__ float As[128 * PJ_STR];
    __shared__ float Bs[64 * PJ_STR];

    const int c0 = blockIdx.x * 64;
    const int r0 = blockIdx.y * 128;
    const int t    = threadIdx.x;
    const int wid  = t >> 5;
    const int lane = t & 31;
    const int gq   = lane >> 2;
    const int tq   = lane & 3;
    const int wi   = wid >> 1;
    const int wd   = wid & 1;

    float acc[2][4][4];
#pragma unroll
    for (int mt = 0; mt < 2; mt++)
#pragma unroll
        for (int nt = 0; nt < 4; nt++)
#pragma unroll
            for (int r = 0; r < 4; r++) acc[mt][nt][r] = 0.0f;

    for (int k0 = 0; k0 < HH; k0 += 32) {
#pragma unroll
        for (int u = 0; u < 4; u++) {
            int l = u * 256 + t;
            int r = l >> 3, cq = l & 7;
            float4 v = *(const float4*)(X + (size_t)(r0 + r) * HH + k0 + cq * 4);
            *(float4*)&As[r * PJ_STR + cq * 4] = v;
        }
#pragma unroll
        for (int u = 0; u < 2; u++) {
            int l = u * 256 + t;
            int r = l >> 3, cq = l & 7;
            float4 v = *(const float4*)(W + (size_t)(c0 + r) * HH + k0 + cq * 4);
            *(float4*)&Bs[r * PJ_STR + cq * 4] = v;
        }
        __syncthreads();

#pragma unroll
        for (int ks = 0; ks < 4; ks++) {
            const int kk = ks * 8;

            uint32_t ah[2][4], al[2][4];
#pragma unroll
            for (int mt = 0; mt < 2; mt++) {
                int m = wi * 32 + mt * 16 + gq;
                split_tf32(As[m * PJ_STR + kk + tq],           ah[mt][0], al[mt][0]);
                split_tf32(As[(m + 8) * PJ_STR + kk + tq],     ah[mt][1], al[mt][1]);
                split_tf32(As[m * PJ_STR + kk + tq + 4],       ah[mt][2], al[mt][2]);
                split_tf32(As[(m + 8) * PJ_STR + kk + tq + 4], ah[mt][3], al[mt][3]);
            }
            uint32_t bh[4][2], bl[4][2];
#pragma unroll
            for (int nt = 0; nt < 4; nt++) {
                int n = wd * 32 + nt * 8 + gq;
                split_tf32(Bs[n * PJ_STR + kk + tq],     bh[nt][0], bl[nt][0]);
                split_tf32(Bs[n * PJ_STR + kk + tq + 4], bh[nt][1], bl[nt][1]);
            }
#pragma unroll
            for (int mt = 0; mt < 2; mt++)
#pragma unroll
                for (int nt = 0; nt < 4; nt++) {
                    MMA_TF32(acc[mt][nt], ah[mt], bh[nt]);
                    MMA_TF32(acc[mt][nt], ah[mt], bl[nt]);
                    MMA_TF32(acc[mt][nt], al[mt], bh[nt]);
                }
        }
        __syncthreads();
    }

    const int h = c0 / HD;
#pragma unroll
    for (int mt = 0; mt < 2; mt++) {
        int row = r0 + wi * 32 + mt * 16 + gq;
        int b = row / SS, s = row % SS;
#pragma unroll
        for (int nt = 0; nt < 4; nt++) {
            int dl = wd * 32 + nt * 8 + 2 * tq;
            float bs0 = bias[c0 + dl];
            float bs1 = bias[c0 + dl + 1];
            float* d0 = Y + (((size_t)(b * NH + h) * SS + s) * HD + dl);
            float* d1 = Y + (((size_t)(b * NH + h) * SS + s + 8) * HD + dl);
            *(float2*)d0 = make_float2(acc[mt][nt][0] + bs0, acc[mt][nt][1] + bs1);
            *(float2*)d1 = make_float2(acc[mt][nt][2] + bs0, acc[mt][nt][3] + bs1);
        }
    }
}

// ---------------------------------------------------------------------------
// Kernel 1c: pack v into fp16 pairs along s.
// ---------------------------------------------------------------------------
__global__ __launch_bounds__(256) void pack_v_kernel()
{
    int u = blockIdx.x * 256 + threadIdx.x;
    int s2row = u >> 4;
    int cq = u & 15;
    const float* p = g_v + (size_t)s2row * 128 + cq * 4;
    float4 a = *(const float4*)p;
    float4 b = *(const float4*)(p + 64);
    uint4 o = make_uint4(f16x2(a.x, b.x), f16x2(a.y, b.y),
                         f16x2(a.z, b.z), f16x2(a.w, b.w));
    *(uint4*)(g_vp + (size_t)s2row * 64 + cq * 4) = o;
}

// ---------------------------------------------------------------------------
// Kernel 2: scores = q @ k^T / 8 + mask via mma.sync 3xTF32 (exact R9 form).
// ---------------------------------------------------------------------------
#define SQ_STR 68
#define SC_SMEM_BYTES (192 * SQ_STR * 4 + 64 * 4)

__global__ __launch_bounds__(256) void scores_mma_kernel(
    const int* __restrict__ mask, float* __restrict__ wbuf)
{
    extern __shared__ float smem[];
    float* Qs = smem;
    float* Ks = smem + 128 * SQ_STR;
    int*   msk = (int*)(smem + 192 * SQ_STR);

    const int j0 = blockIdx.x * 64;
    const int i0 = blockIdx.y * 128;
    const int z  = blockIdx.z;
    const int bidx = z / NH;
    const int t    = threadIdx.x;
    const int wid  = t >> 5;
    const int lane = t & 31;
    const int gq   = lane >> 2;
    const int tq   = lane & 3;
    const int wi   = wid >> 1;
    const int wd   = wid & 1;

    const float* qbase = g_q + ((size_t)z * SS + i0) * HD;
    const float* kbase = g_k + ((size_t)z * SS + j0) * HD;

#pragma unroll
    for (int u = 0; u < 8; u++) {
        int l = u * 256 + t;
        int r = l >> 4, cq = l & 15;
        float4 v = ((const float4*)qbase)[l];
        *(float4*)&Qs[r * SQ_STR + cq * 4] = v;
    }
#pragma unroll
    for (int u = 0; u < 4; u++) {
        int l = u * 256 + t;
        int r = l >> 4, cq = l & 15;
        float4 v = ((const float4*)kbase)[l];
        *(float4*)&Ks[r * SQ_STR + cq * 4] = v;
    }
    if (t < 64) msk[t] = mask[(size_t)bidx * SS + j0 + t];
    __syncthreads();

    float acc[2][4][4];
#pragma unroll
    for (int mt = 0; mt < 2; mt++)
#pragma unroll
        for (int nt = 0; nt < 4; nt++)
#pragma unroll
            for (int r = 0; r < 4; r++) acc[mt][nt][r] = 0.0f;

#pragma unroll
    for (int ks = 0; ks < 8; ks++) {
        const int kk = ks * 8;

        uint32_t ah[2][4], al[2][4];
#pragma unroll
        for (int mt = 0; mt < 2; mt++) {
            int m = wi * 32 + mt * 16 + gq;
            split_tf32(Qs[m * SQ_STR + kk + tq],           ah[mt][0], al[mt][0]);
            split_tf32(Qs[(m + 8) * SQ_STR + kk + tq],     ah[mt][1], al[mt][1]);
            split_tf32(Qs[m * SQ_STR + kk + tq + 4],       ah[mt][2], al[mt][2]);
            split_tf32(Qs[(m + 8) * SQ_STR + kk + tq + 4], ah[mt][3], al[mt][3]);
        }
        uint32_t bh[4][2], bl[4][2];
#pragma unroll
        for (int nt = 0; nt < 4; nt++) {
            int n = wd * 32 + nt * 8 + gq;
            split_tf32(Ks[n * SQ_STR + kk + tq],     bh[nt][0], bl[nt][0]);
            split_tf32(Ks[n * SQ_STR + kk + tq + 4], bh[nt][1], bl[nt][1]);
        }
#pragma unroll
        for (int mt = 0; mt < 2; mt++)
#pragma unroll
            for (int nt = 0; nt < 4; nt++) {
                MMA_TF32(acc[mt][nt], ah[mt], bh[nt]);
                MMA_TF32(acc[mt][nt], ah[mt], bl[nt]);
                MMA_TF32(acc[mt][nt], al[mt], bh[nt]);
            }
    }

    const float NEG_INF = __int_as_float(0xff800000);
#pragma unroll
    for (int mt = 0; mt < 2; mt++) {
        int r = i0 + wi * 32 + mt * 16 + gq;
#pragma unroll
        for (int nt = 0; nt < 4; nt++) {
            int jl = wd * 32 + nt * 8 + 2 * tq;
            int m0 = msk[jl], m1 = msk[jl + 1];
            float v0 = (m0 > 0) ? NEG_INF : acc[mt][nt][0] * 0.125f;
            float v1 = (m1 > 0) ? NEG_INF : acc[mt][nt][1] * 0.125f;
            float v2 = (m0 > 0) ? NEG_INF : acc[mt][nt][2] * 0.125f;
            float v3 = (m1 > 0) ? NEG_INF : acc[mt][nt][3] * 0.125f;
            float* d0 = wbuf + ((size_t)z * SS + r) * SS + j0 + jl;
            float* d1 = wbuf + ((size_t)z * SS + r + 8) * SS + j0 + jl;
            *(float2*)d0 = make_float2(v0, v1);
            *(float2*)d1 = make_float2(v2, v3);
        }
    }
}

// ---------------------------------------------------------------------------
// Kernel 3: softmax + threshold + L1 renorm (divide-free); ALSO emits
// fp16-packed w pairs (R12/R14-validated; av output bit-identical).
// ---------------------------------------------------------------------------
__device__ __forceinline__ float warpMax(float v) {
#pragma unroll
    for (int o = 16; o; o >>= 1) v = fmaxf(v, __shfl_xor_sync(0xffffffffu, v, o));
    return v;
}
__device__ __forceinline__ float warpSum(float v) {
#pragma unroll
    for (int o = 16; o; o >>= 1) v += __shfl_xor_sync(0xffffffffu, v, o);
    return v;
}
__device__ float blockMax(float v, float* red) {
    v = warpMax(v);
    int w = threadIdx.x >> 5, lane = threadIdx.x & 31;
    if (lane == 0) red[w] = v;
    __syncthreads();
    float r = (lane < 8) ? red[lane] : __int_as_float(0xff800000);
    if (w == 0) { r = warpMax(r); if (lane == 0) red[0] = r; }
    __syncthreads();
    float out = red[0];
    __syncthreads();
    return out;
}
__device__ float blockSum(float v, float* red) {
    v = warpSum(v);
    int w = threadIdx.x >> 5, lane = threadIdx.x & 31;
    if (lane == 0) red[w] = v;
    __syncthreads();
    float r = (lane < 8) ? red[lane] : 0.0f;
    if (w == 0) { r = warpSum(r); if (lane == 0) red[0] = r; }
    __syncthreads();
    float out = red[0];
    __syncthreads();
    return out;
}

__global__ __launch_bounds__(256) void softmax_kernel(float* __restrict__ wbuf)
{
    __shared__ float red[8];
    const size_t row = blockIdx.x;
    float* p = wbuf + row * SS;
    uint32_t* wp = g_wp + row * (SS / 2);
    const int t = threadIdx.x;

    float4 x0 = ((const float4*)p)[t];
    float4 x1 = ((const float4*)p)[t + 256];
    float v[8] = {x0.x, x0.y, x0.z, x0.w, x1.x, x1.y, x1.z, x1.w};

    float m = v[0];
#pragma unroll
    for (int i = 1; i < 8; i++) m = fmaxf(m, v[i]);
    m = blockMax(m, red);

    float e[8], es = 0.0f;
#pragma unroll
    for (int i = 0; i < 8; i++) { e[i] = expf(v[i] - m); es += e[i]; }
    es = blockSum(es, red);

    const float tes = 0.001f * es;
    const float inv_es = 1.0f / es;

    float w[8], l1 = 0.0f;
#pragma unroll
    for (int i = 0; i < 8; i++) {
        float wi = (e[i] < tes) ? 0.0f : e[i] * inv_es;
        w[i] = wi;
        l1 += wi;
    }
    l1 = blockSum(l1, red);
    float rinv = 1.0f / fmaxf(l1, 1e-12f);

#pragma unroll
    for (int i = 0; i < 8; i++) w[i] *= rinv;

    float4 o0 = make_float4(w[0], w[1], w[2], w[3]);
    float4 o1 = make_float4(w[4], w[5], w[6], w[7]);
    ((float4*)p)[t]       = o0;
    ((float4*)p)[t + 256] = o1;

    uint2 h0 = make_uint2(f16x2(w[0], w[1]), f16x2(w[2], w[3]));
    uint2 h1 = make_uint2(f16x2(w[4], w[5]), f16x2(w[6], w[7]));
    *(uint2*)(wp + 2 * t)       = h0;
    *(uint2*)(wp + 512 + 2 * t) = h1;
}

// ---------------------------------------------------------------------------
// Kernel 4: out = w @ v via fp16 mma.sync, reading pre-packed fp16 w
// (R14-validated form: single-buffered, AVW_STR=20).
// ---------------------------------------------------------------------------
#define AVW_STR 20
#define AVV_STR 72

__global__ __launch_bounds__(256) void av_f16_kernel(float* __restrict__ out)
{
    __shared__ uint32_t Wh[128 * AVW_STR];
    __shared__ uint32_t Vp[16 * AVV_STR];

    const int t    = threadIdx.x;
    const int wid  = t >> 5;
    const int lane = t & 31;
    const int gq   = lane >> 2;
    const int tq   = lane & 3;
    const int wi   = wid >> 1;
    const int wd   = wid & 1;

    const int i0 = blockIdx.x * 128;
    const int z  = blockIdx.y;
    const int bidx = z / NH;
    const int h    = z % NH;

    const uint32_t* Wp16   = g_wp + ((size_t)z * SS + i0) * (SS / 2);
    const uint32_t* Vpbase = g_vp + (size_t)z * (SS / 2) * HD;

    float acc[2][4][4];
#pragma unroll
    for (int mt = 0; mt < 2; mt++)
#pragma unroll
        for (int nt = 0; nt < 4; nt++)
#pragma unroll
            for (int r = 0; r < 4; r++) acc[mt][nt][r] = 0.0f;

    for (int c = 0; c < SS / 32; c++) {
#pragma unroll
        for (int u = 0; u < 2; u++) {
            int l = u * 256 + t;
            int r = l >> 2, q4 = l & 3;
            uint4 v = *(const uint4*)(Wp16 + (size_t)r * (SS / 2) + c * 16 + q4 * 4);
            *(uint4*)&Wh[r * AVW_STR + q4 * 4] = v;
        }
        {
            int r = t >> 4, cq = t & 15;
            uint4 pv = *(const uint4*)(Vpbase + (size_t)(c * 16 + r) * HD + cq * 4);
            *(uint4*)&Vp[r * AVV_STR + cq * 4] = pv;
        }
        __syncthreads();

#pragma unroll
        for (int ks = 0; ks < 2; ks++) {
            uint32_t a[2][4];
#pragma unroll
            for (int mt = 0; mt < 2; mt++) {
                int m = wi * 32 + mt * 16 + gq;
                a[mt][0] = Wh[m * AVW_STR + ks * 8 + tq];
                a[mt][1] = Wh[(m + 8) * AVW_STR + ks * 8 + tq];
                a[mt][2] = Wh[m * AVW_STR + ks * 8 + tq + 4];
                a[mt][3] = Wh[(m + 8) * AVW_STR + ks * 8 + tq + 4];
            }
            uint32_t b[4][2];
#pragma unroll
            for (int nt = 0; nt < 4; nt++) {
                int n = wd * 32 + nt * 8 + gq;
                b[nt][0] = Vp[(ks * 8 + tq) * AVV_STR + n];
                b[nt][1] = Vp[(ks * 8 + tq + 4) * AVV_STR + n];
            }
#pragma unroll
            for (int mt = 0; mt < 2; mt++)
#pragma unroll
                for (int nt = 0; nt < 4; nt++)
                    MMA_F16(acc[mt][nt], a[mt], b[nt]);
        }
        __syncthreads();
    }

#pragma unroll
    for (int mt = 0; mt < 2; mt++) {
        int row = i0 + wi * 32 + mt * 16 + gq;
#pragma unroll
        for (int nt = 0; nt < 4; nt++) {
            int col = h * HD + wd * 32 + nt * 8 + 2 * tq;
            float* d0 = out + ((size_t)bidx * SS + row) * HH + col;
            float* d1 = out + ((size_t)bidx * SS + row + 8) * HH + col;
            *(float2*)d0 = make_float2(acc[mt][nt][0], acc[mt][nt][1]);
            *(float2*)d1 = make_float2(acc[mt][nt][2], acc[mt][nt][3]);
        }
    }
}

// ---------------------------------------------------------------------------
extern "C" void kernel_launch(void* const* d_in, const int* in_sizes, int n_in,
                              void* d_out, int out_size)
{
    const float* query = (const float*)d_in[0];
    const float* key   = (const float*)d_in[1];
    const float* value = (const float*)d_in[2];
    const int*   mask  = (const int*)  d_in[3];
    const float* Wq    = (const float*)d_in[4];
    const float* bq    = (const float*)d_in[5];
    const float* Wk    = (const float*)d_in[6];
    const float* bk    = (const float*)d_in[7];
    const float* Wv    = (const float*)d_in[8];
    const float* bv    = (const float*)d_in[9];

    float* out  = (float*)d_out;
    float* wbuf = out + (size_t)BB * SS * HH;

    float* vp;
    cudaGetSymbolAddress((void**)&vp, g_v);

    // 0) Fused split of query/key/Wq/Wk into lossless bf16 triples
    int nblk = (int)((TOTAL_PAIRS + 255) / 256);
    split3_all_kernel<<<nblk, 256>>>(query, key, Wq, Wk);

    // 1) q/k projections via 6xBF16 with per-chunk accumulators (R9)
    dim3 gProj(HH / 64, XROWS / 128, 2);        // (16, 32, 2)
    proj6_kernel<<<gProj, 256>>>(bq, bk);

    // 1b) v projection via 3xTF32 (error-safe)
    dim3 gProjV(HH / 64, XROWS / 128);          // (16, 32)
    projv_mma_kernel<<<gProjV, 256>>>(value, Wv, bv, vp);

    // 1c) pack v -> fp16 pairs
    pack_v_kernel<<<(QKV_ELEMS / 8) / 256, 256>>>();

    // 2) Scores via 3xTF32 mma.sync (R9)
    cudaFuncSetAttribute(scores_mma_kernel,
                         cudaFuncAttributeMaxDynamicSharedMemorySize,
                         SC_SMEM_BYTES);
    dim3 gScores(SS / 64, SS / 128, BB * NH);   // (32, 16, 32)
    scores_mma_kernel<<<gScores, 256, SC_SMEM_BYTES>>>(mask, wbuf);

    // 3) Softmax + threshold + L1 renorm; emits fp32 w + fp16-packed w
    softmax_kernel<<<BB * NH * SS, 256>>>(wbuf);

    // 4) out = w @ v via fp16 mma.sync (reads fp16 w)
    dim3 gAV(SS / 128, BB * NH);
    av_f16_kernel<<<gAV, 256>>>(out);
}